// round 12
// baseline (speedup 1.0000x reference)
#include <cuda_runtime.h>
#include <cuda_fp16.h>
#include <cstdint>

#define N_USERS 100000
#define N_ITEMS 50000
#define N_NODES 150000
#define D 64
#define DH2 32             // D/2 half2 per node row (128B)
#define DU4 8              // D/8 uint4 per node row (128B)
#define NNZ 4800000
#define PAD 128            // slots per row (Poisson(32) max deg << 128)
#define PAD_SHIFT 7
#define NBUCKET 16

// ---------------- device-global scratch (no allocations allowed) -----------
__device__ uint4 g_egoH[N_NODES * DU4];            // 19.2 MB fp16 ego
__device__ uint4 g_bufA[N_NODES * DU4];            // 19.2 MB hop-1 out
__device__ uint4 g_bufB[N_NODES * DU4];            // 19.2 MB hop-2 out
__device__ int2  g_colvPad[N_NODES * PAD + 64];    // 153.6 MB padded CSR (+prefetch guard)
__device__ int   g_cntPad[N_NODES * 8];            // counters, 32B stride
__device__ int   g_bkt[NBUCKET];                   // bucket counts
__device__ int   g_bktCur[NBUCKET];                // bucket cursors (bases)
__device__ int   g_rmap[N_NODES];                  // degree-bucketed row order

// ---------------------------------------------------------------------------
// ego fp32 -> fp16 (concat fused)
// ---------------------------------------------------------------------------
__global__ void __launch_bounds__(256) convert_kernel(
    const float2* __restrict__ u, const float2* __restrict__ it,
    __half2* __restrict__ egoH)
{
    int i = blockIdx.x * blockDim.x + threadIdx.x;
    const int total = N_NODES * DH2;
    const int nu = N_USERS * DH2;                  // user rows * 32 float2
    if (i < total) {
        float2 v = (i < nu) ? __ldcs(u + i) : __ldcs(it + (i - nu));
        egoH[i] = __float22half2_rn(v);
    }
}

// ---------------------------------------------------------------------------
// Padded-slot CSR build: one atomic pass, counters padded to 32B stride.
// ---------------------------------------------------------------------------
__global__ void __launch_bounds__(256) scatter_kernel(
    const int4* __restrict__ row4, const int4* __restrict__ col4,
    const float4* __restrict__ vals4)
{
    int i = blockIdx.x * blockDim.x + threadIdx.x;
    if (i >= NNZ / 4) return;
    int4   r = __ldcs(row4 + i);
    int4   c = __ldcs(col4 + i);
    float4 v = __ldcs(vals4 + i);
    int p0 = atomicAdd(&g_cntPad[r.x << 3], 1) & (PAD - 1);
    int p1 = atomicAdd(&g_cntPad[r.y << 3], 1) & (PAD - 1);
    int p2 = atomicAdd(&g_cntPad[r.z << 3], 1) & (PAD - 1);
    int p3 = atomicAdd(&g_cntPad[r.w << 3], 1) & (PAD - 1);
    __stcs(&g_colvPad[((size_t)r.x << PAD_SHIFT) + p0],
           make_int2(c.x, __float_as_int(v.x)));
    __stcs(&g_colvPad[((size_t)r.y << PAD_SHIFT) + p1],
           make_int2(c.y, __float_as_int(v.y)));
    __stcs(&g_colvPad[((size_t)r.z << PAD_SHIFT) + p2],
           make_int2(c.z, __float_as_int(v.z)));
    __stcs(&g_colvPad[((size_t)r.w << PAD_SHIFT) + p3],
           make_int2(c.w, __float_as_int(v.w)));
}

// ---------------------------------------------------------------------------
// Degree bucketing: rows grouped by chunk count so each hop warp's 4 rows
// have identical trip counts (kills intra-warp divergence).
// ---------------------------------------------------------------------------
__global__ void __launch_bounds__(256) bucket_count_kernel()
{
    int i = blockIdx.x * blockDim.x + threadIdx.x;
    if (i < N_NODES) {
        int d = g_cntPad[i << 3];
        int b = min((d + 15) >> 4, NBUCKET - 1);
        atomicAdd(&g_bkt[b], 1);
    }
}

__global__ void __launch_bounds__(32) bucket_scan_kernel()
{
    int l = threadIdx.x;
    int c = (l < NBUCKET) ? g_bkt[l] : 0;
    int v = c;
    #pragma unroll
    for (int o = 1; o < NBUCKET; o <<= 1) {
        int t = __shfl_up_sync(0xFFFFFFFF, v, o);
        if (l >= o) v += t;
    }
    if (l < NBUCKET) g_bktCur[l] = v - c;          // exclusive prefix
}

__global__ void __launch_bounds__(256) place_kernel()
{
    int i = blockIdx.x * blockDim.x + threadIdx.x;
    if (i < N_NODES) {
        int d = g_cntPad[i << 3];
        int b = min((d + 15) >> 4, NBUCKET - 1);
        int pos = atomicAdd(&g_bktCur[b], 1);
        g_rmap[pos] = i;
    }
}

// ---------------------------------------------------------------------------
// Gather SpMM hop: 4 rows/warp (bucket-matched), 8 lanes/row, lane owns 16B
// (8 dims) via LDG.128. 16-edge metadata chunks loaded as int4 (2 edges/lane),
// software-pipelined; shfl-fed independent gathers.
// MODE 1: x=egoH; yh=bufA, out_layer = y1
// MODE 2: x=bufA; yh=bufB
// MODE 3: x=bufB; out_all = (bufA + bufB + y3)/3
// ---------------------------------------------------------------------------
template<int MODE>
__global__ void __launch_bounds__(256) hop_kernel(
    const uint4* __restrict__ xh, uint4* __restrict__ yh,
    const uint4* __restrict__ y1h, const uint4* __restrict__ y2h,
    float4* __restrict__ out_all, float4* __restrict__ out_layer)
{
    int gwarp = (blockIdx.x * blockDim.x + threadIdx.x) >> 5;
    int lane  = threadIdx.x & 31;
    int grp   = lane >> 3;
    int sub   = lane & 7;
    int rbase = gwarp << 2;
    if (rbase >= N_NODES) return;

    int row = __ldg(&g_rmap[rbase + grp]);
    const unsigned mask = 0xFFu << (grp << 3);
    int beg = row << PAD_SHIFT;                    // edge index of slot 0
    int deg = min(g_cntPad[row << 3], PAD);
    int nfull = deg >> 4;

    const int4* colv4 = (const int4*)g_colvPad;
    int cbase = (beg >> 1) + sub;                  // int4 slot for this lane

    float a0=0.f,a1=0.f,a2=0.f,a3=0.f,a4=0.f,a5=0.f,a6=0.f,a7=0.f;

    int4 cv = __ldcs(&colv4[cbase]);               // chunk 0 (2 edges/lane)
    for (int c = 0; c < nfull; c++) {
        int4 cur = cv;
        cv = __ldcs(&colv4[cbase + (c + 1) * 8]);  // prefetch next chunk
        #pragma unroll
        for (int j = 0; j < 16; j++) {
            int cx = (j & 1) ? __shfl_sync(mask, cur.z, j >> 1, 8)
                             : __shfl_sync(mask, cur.x, j >> 1, 8);
            int vb = (j & 1) ? __shfl_sync(mask, cur.w, j >> 1, 8)
                             : __shfl_sync(mask, cur.y, j >> 1, 8);
            uint4 h = __ldg(xh + (size_t)cx * DU4 + sub);
            float v = __int_as_float(vb);
            float2 f0 = __half22float2(*reinterpret_cast<__half2*>(&h.x));
            float2 f1 = __half22float2(*reinterpret_cast<__half2*>(&h.y));
            float2 f2 = __half22float2(*reinterpret_cast<__half2*>(&h.z));
            float2 f3 = __half22float2(*reinterpret_cast<__half2*>(&h.w));
            a0 = fmaf(v, f0.x, a0); a1 = fmaf(v, f0.y, a1);
            a2 = fmaf(v, f1.x, a2); a3 = fmaf(v, f1.y, a3);
            a4 = fmaf(v, f2.x, a4); a5 = fmaf(v, f2.y, a5);
            a6 = fmaf(v, f3.x, a6); a7 = fmaf(v, f3.y, a7);
        }
    }

    int rem = deg - (nfull << 4);                  // group-uniform
    #pragma unroll
    for (int j = 0; j < 16; j++) {
        if (j < rem) {
            int cx = (j & 1) ? __shfl_sync(mask, cv.z, j >> 1, 8)
                             : __shfl_sync(mask, cv.x, j >> 1, 8);
            int vb = (j & 1) ? __shfl_sync(mask, cv.w, j >> 1, 8)
                             : __shfl_sync(mask, cv.y, j >> 1, 8);
            uint4 h = __ldg(xh + (size_t)cx * DU4 + sub);
            float v = __int_as_float(vb);
            float2 f0 = __half22float2(*reinterpret_cast<__half2*>(&h.x));
            float2 f1 = __half22float2(*reinterpret_cast<__half2*>(&h.y));
            float2 f2 = __half22float2(*reinterpret_cast<__half2*>(&h.z));
            float2 f3 = __half22float2(*reinterpret_cast<__half2*>(&h.w));
            a0 = fmaf(v, f0.x, a0); a1 = fmaf(v, f0.y, a1);
            a2 = fmaf(v, f1.x, a2); a3 = fmaf(v, f1.y, a3);
            a4 = fmaf(v, f2.x, a4); a5 = fmaf(v, f2.y, a5);
            a6 = fmaf(v, f3.x, a6); a7 = fmaf(v, f3.y, a7);
        }
    }

    size_t ou = (size_t)row * DU4 + sub;           // uint4 slot in fp16 bufs
    size_t of = (size_t)row * 16 + sub * 2;        // float4 slots in d_out

    if (MODE == 1 || MODE == 2) {
        __half2 p0 = __floats2half2_rn(a0, a1);
        __half2 p1 = __floats2half2_rn(a2, a3);
        __half2 p2 = __floats2half2_rn(a4, a5);
        __half2 p3 = __floats2half2_rn(a6, a7);
        uint4 pk;
        pk.x = *reinterpret_cast<unsigned*>(&p0);
        pk.y = *reinterpret_cast<unsigned*>(&p1);
        pk.z = *reinterpret_cast<unsigned*>(&p2);
        pk.w = *reinterpret_cast<unsigned*>(&p3);
        __stcs(&yh[ou], pk);
    }
    if (MODE == 1) {
        __stcs(&out_layer[of],     make_float4(a0, a1, a2, a3));
        __stcs(&out_layer[of + 1], make_float4(a4, a5, a6, a7));
    }
    if (MODE == 3) {
        const float s = 1.0f / 3.0f;
        uint4 u1 = __ldcs(y1h + ou);
        uint4 u2 = __ldcs(y2h + ou);
        float2 b10 = __half22float2(*reinterpret_cast<__half2*>(&u1.x));
        float2 b11 = __half22float2(*reinterpret_cast<__half2*>(&u1.y));
        float2 b12 = __half22float2(*reinterpret_cast<__half2*>(&u1.z));
        float2 b13 = __half22float2(*reinterpret_cast<__half2*>(&u1.w));
        float2 b20 = __half22float2(*reinterpret_cast<__half2*>(&u2.x));
        float2 b21 = __half22float2(*reinterpret_cast<__half2*>(&u2.y));
        float2 b22 = __half22float2(*reinterpret_cast<__half2*>(&u2.z));
        float2 b23 = __half22float2(*reinterpret_cast<__half2*>(&u2.w));
        __stcs(&out_all[of], make_float4(
            (b10.x + b20.x + a0) * s, (b10.y + b20.y + a1) * s,
            (b11.x + b21.x + a2) * s, (b11.y + b21.y + a3) * s));
        __stcs(&out_all[of + 1], make_float4(
            (b12.x + b22.x + a4) * s, (b12.y + b22.y + a5) * s,
            (b13.x + b23.x + a6) * s, (b13.y + b23.y + a7) * s));
    }
}

// ---------------------------------------------------------------------------
extern "C" void kernel_launch(void* const* d_in, const int* in_sizes, int n_in,
                              void* d_out, int out_size)
{
    const float2* user_e = (const float2*)d_in[0];
    const float2* item_e = (const float2*)d_in[1];
    const int*    row    = (const int*)d_in[2];
    const int*    col    = (const int*)d_in[3];
    const float*  vals   = (const float*)d_in[4];

    float4* out_all   = (float4*)d_out;
    float4* out_layer = out_all + (size_t)N_NODES * 16;

    void *cntAddr, *bktAddr;
    cudaGetSymbolAddress(&cntAddr, g_cntPad);
    cudaGetSymbolAddress(&bktAddr, g_bkt);
    uint4 *egoH, *bufA, *bufB;
    cudaGetSymbolAddress((void**)&egoH, g_egoH);
    cudaGetSymbolAddress((void**)&bufA, g_bufA);
    cudaGetSymbolAddress((void**)&bufB, g_bufB);

    const int edge4Blocks = (NNZ / 4 + 255) / 256;
    const int nodeBlocks  = (N_NODES + 255) / 256;
    const int elemBlocks  = (N_NODES * DH2 + 255) / 256;
    const int hopWarps    = N_NODES / 4;               // 4 rows per warp
    const int hopBlocks   = (hopWarps * 32 + 255) / 256;

    // ---- fp16 ego + one-pass padded CSR build + degree bucketing ----
    convert_kernel<<<elemBlocks, 256>>>(user_e, item_e, (__half2*)egoH);
    cudaMemsetAsync(cntAddr, 0, N_NODES * 8 * sizeof(int));
    cudaMemsetAsync(bktAddr, 0, NBUCKET * sizeof(int));
    scatter_kernel<<<edge4Blocks, 256>>>((const int4*)row, (const int4*)col,
                                         (const float4*)vals);
    bucket_count_kernel<<<nodeBlocks, 256>>>();
    bucket_scan_kernel<<<1, 32>>>();
    place_kernel<<<nodeBlocks, 256>>>();

    // ---- 3 hops; mean deferred to hop 3 ----
    hop_kernel<1><<<hopBlocks, 256>>>(egoH, bufA, nullptr, nullptr,
                                      out_all, out_layer);
    hop_kernel<2><<<hopBlocks, 256>>>(bufA, bufB, nullptr, nullptr,
                                      out_all, out_layer);
    hop_kernel<3><<<hopBlocks, 256>>>(bufB, nullptr, bufA, bufB,
                                      out_all, out_layer);
}

// round 14
// speedup vs baseline: 1.1950x; 1.1950x over previous
#include <cuda_runtime.h>
#include <cuda_fp16.h>
#include <cstdint>

#define N_USERS 100000
#define N_ITEMS 50000
#define N_NODES 150000
#define D 64
#define DH2 32             // D/2 half2 per node row (128B)
#define DU2 16             // D/4 uint2 per node row (128B)
#define DF2 32             // D/2 float2 per node row (256B)
#define NNZ 4800000
#define PAD 128            // slots per row (Poisson(32) max deg << 128)
#define PAD_SHIFT 7

// ---------------- device-global scratch (no allocations allowed) -----------
__device__ uint2 g_egoH[N_NODES * DU2];        // 19.2 MB fp16 ego
__device__ uint2 g_bufA[N_NODES * DU2];        // 19.2 MB hop-1 out (fp16)
__device__ uint2 g_bufB[N_NODES * DU2];        // 19.2 MB hop-2 out (fp16)
__device__ int2  g_colvPad[N_NODES * PAD + 32];// 153.6 MB padded CSR slots
__device__ int   g_cnt[N_NODES];               // per-row fill counters == degree

// ---------------------------------------------------------------------------
// ego fp32 -> fp16 (concat fused)
// ---------------------------------------------------------------------------
__global__ void __launch_bounds__(256) convert_kernel(
    const float2* __restrict__ u, const float2* __restrict__ it,
    __half2* __restrict__ egoH)
{
    int i = blockIdx.x * blockDim.x + threadIdx.x;
    const int total = N_NODES * DH2;
    const int nu = N_USERS * DF2;
    if (i < total) {
        float2 v = (i < nu) ? __ldcs(u + i) : __ldcs(it + (i - nu));
        egoH[i] = __float22half2_rn(v);
    }
}

// ---------------------------------------------------------------------------
// Padded-slot CSR build: ONE atomic pass (identical to R10's proven version).
// ---------------------------------------------------------------------------
__global__ void __launch_bounds__(256) scatter_kernel(
    const int4* __restrict__ row4, const int4* __restrict__ col4,
    const float4* __restrict__ vals4)
{
    int i = blockIdx.x * blockDim.x + threadIdx.x;
    if (i >= NNZ / 4) return;
    int4   r = __ldcs(row4 + i);
    int4   c = __ldcs(col4 + i);
    float4 v = __ldcs(vals4 + i);
    int p0 = atomicAdd(&g_cnt[r.x], 1) & (PAD - 1);
    int p1 = atomicAdd(&g_cnt[r.y], 1) & (PAD - 1);
    int p2 = atomicAdd(&g_cnt[r.z], 1) & (PAD - 1);
    int p3 = atomicAdd(&g_cnt[r.w], 1) & (PAD - 1);
    __stcs(&g_colvPad[((size_t)r.x << PAD_SHIFT) + p0],
           make_int2(c.x, __float_as_int(v.x)));
    __stcs(&g_colvPad[((size_t)r.y << PAD_SHIFT) + p1],
           make_int2(c.y, __float_as_int(v.y)));
    __stcs(&g_colvPad[((size_t)r.z << PAD_SHIFT) + p2],
           make_int2(c.z, __float_as_int(v.z)));
    __stcs(&g_colvPad[((size_t)r.w << PAD_SHIFT) + p3],
           make_int2(c.w, __float_as_int(v.w)));
}

// ---------------------------------------------------------------------------
// Gather SpMM hop (R10 layout: 2 rows/warp, 16 lanes/row, lane owns uint2).
// SINGLE CHANGE vs R10: the 16-edge chunk is processed as two 8-edge batches
// with explicit address/data arrays, forcing ~8 gathers in flight per warp
// before any FMA drains them (raises MLP at the cost of ~48 regs).
// MODE 1: x=egoH; yh=bufA, out_layer = y1
// MODE 2: x=bufA; yh=bufB
// MODE 3: x=bufB; out_all = (bufA + bufB + y3)/3
// ---------------------------------------------------------------------------
template<int MODE>
__global__ void __launch_bounds__(256) hop_kernel(
    const uint2* __restrict__ xh, uint2* __restrict__ yh,
    const uint2* __restrict__ y1h, const uint2* __restrict__ y2h,
    float2* __restrict__ out_all, float2* __restrict__ out_layer)
{
    int gwarp = (blockIdx.x * blockDim.x + threadIdx.x) >> 5;
    int lane  = threadIdx.x & 31;
    int half  = lane >> 4;
    int sub   = lane & 15;
    int row   = gwarp * 2 + half;
    if (row >= N_NODES) return;

    const unsigned mask = 0xFFFFu << (half << 4);
    int beg = row << PAD_SHIFT;
    int deg = min(g_cnt[row], PAD);
    int end = beg + deg;
    int nfull = deg >> 4;

    float a0 = 0.f, a1 = 0.f, a2 = 0.f, a3 = 0.f;

    // prime chunk 0
    int2 cv = (sub < deg) ? __ldcs(&g_colvPad[beg + sub]) : make_int2(0, 0);
    int base = beg;

    for (int c = 0; c < nfull; c++) {
        int2 cur = cv;
        cv = __ldcs(&g_colvPad[base + 16 + sub]);          // prefetch (padded)
        #pragma unroll
        for (int b = 0; b < 2; b++) {                      // two 8-edge batches
            uint2 h[8];
            float v[8];
            #pragma unroll
            for (int j = 0; j < 8; j++) {                  // issue 8 gathers
                int cx = __shfl_sync(mask, cur.x, b * 8 + j, 16);
                int vb = __shfl_sync(mask, cur.y, b * 8 + j, 16);
                v[j] = __int_as_float(vb);
                h[j] = __ldg(xh + (size_t)cx * DU2 + sub);
            }
            #pragma unroll
            for (int j = 0; j < 8; j++) {                  // drain FMAs
                float2 f0 = __half22float2(*reinterpret_cast<__half2*>(&h[j].x));
                float2 f1 = __half22float2(*reinterpret_cast<__half2*>(&h[j].y));
                a0 = fmaf(v[j], f0.x, a0);
                a1 = fmaf(v[j], f0.y, a1);
                a2 = fmaf(v[j], f1.x, a2);
                a3 = fmaf(v[j], f1.y, a3);
            }
        }
        base += 16;
    }

    int rem = end - base;
    #pragma unroll
    for (int j = 0; j < 16; j++) {
        if (j < rem) {
            int cx = __shfl_sync(mask, cv.x, j, 16);
            int vb = __shfl_sync(mask, cv.y, j, 16);
            uint2 h = __ldg(xh + (size_t)cx * DU2 + sub);
            float v = __int_as_float(vb);
            float2 f0 = __half22float2(*reinterpret_cast<__half2*>(&h.x));
            float2 f1 = __half22float2(*reinterpret_cast<__half2*>(&h.y));
            a0 = fmaf(v, f0.x, a0);
            a1 = fmaf(v, f0.y, a1);
            a2 = fmaf(v, f1.x, a2);
            a3 = fmaf(v, f1.y, a3);
        }
    }

    size_t oh = (size_t)row * DU2 + sub;          // fp16 buffer slot
    size_t of = (size_t)row * DF2 + sub * 2;      // fp32 float2 slot (x2)

    if (MODE == 1 || MODE == 2) {
        __half2 p0 = __floats2half2_rn(a0, a1);
        __half2 p1 = __floats2half2_rn(a2, a3);
        uint2 packed;
        packed.x = *reinterpret_cast<unsigned*>(&p0);
        packed.y = *reinterpret_cast<unsigned*>(&p1);
        __stcs(&yh[oh], packed);
    }
    if (MODE == 1) {
        __stcs(&out_layer[of],     make_float2(a0, a1));
        __stcs(&out_layer[of + 1], make_float2(a2, a3));
    }
    if (MODE == 3) {
        const float s = 1.0f / 3.0f;
        uint2 u1 = __ldcs(y1h + oh);
        uint2 u2 = __ldcs(y2h + oh);
        float2 b10 = __half22float2(*reinterpret_cast<__half2*>(&u1.x));
        float2 b11 = __half22float2(*reinterpret_cast<__half2*>(&u1.y));
        float2 b20 = __half22float2(*reinterpret_cast<__half2*>(&u2.x));
        float2 b21 = __half22float2(*reinterpret_cast<__half2*>(&u2.y));
        __stcs(&out_all[of],
               make_float2((b10.x + b20.x + a0) * s, (b10.y + b20.y + a1) * s));
        __stcs(&out_all[of + 1],
               make_float2((b11.x + b21.x + a2) * s, (b11.y + b21.y + a3) * s));
    }
}

// ---------------------------------------------------------------------------
extern "C" void kernel_launch(void* const* d_in, const int* in_sizes, int n_in,
                              void* d_out, int out_size)
{
    const float2* user_e = (const float2*)d_in[0];
    const float2* item_e = (const float2*)d_in[1];
    const int*    row    = (const int*)d_in[2];
    const int*    col    = (const int*)d_in[3];
    const float*  vals   = (const float*)d_in[4];

    float2* out_all   = (float2*)d_out;
    float2* out_layer = out_all + (size_t)N_NODES * DF2;

    void* cntAddr;
    cudaGetSymbolAddress(&cntAddr, g_cnt);
    uint2 *egoH, *bufA, *bufB;
    cudaGetSymbolAddress((void**)&egoH, g_egoH);
    cudaGetSymbolAddress((void**)&bufA, g_bufA);
    cudaGetSymbolAddress((void**)&bufB, g_bufB);

    const int edge4Blocks = (NNZ / 4 + 255) / 256;
    const int elemBlocks  = (N_NODES * DH2 + 255) / 256;
    const int hopWarps    = (N_NODES + 1) / 2;              // 2 rows per warp
    const int hopBlocks   = (hopWarps * 32 + 255) / 256;

    // ---- fp16 ego + one-pass padded CSR build ----
    convert_kernel<<<elemBlocks, 256>>>(user_e, item_e, (__half2*)egoH);
    cudaMemsetAsync(cntAddr, 0, N_NODES * sizeof(int));
    scatter_kernel<<<edge4Blocks, 256>>>((const int4*)row, (const int4*)col,
                                         (const float4*)vals);

    // ---- 3 hops; mean deferred to hop 3 ----
    hop_kernel<1><<<hopBlocks, 256>>>(egoH, bufA, nullptr, nullptr,
                                      out_all, out_layer);
    hop_kernel<2><<<hopBlocks, 256>>>(bufA, bufB, nullptr, nullptr,
                                      out_all, out_layer);
    hop_kernel<3><<<hopBlocks, 256>>>(bufB, nullptr, bufA, bufB,
                                      out_all, out_layer);
}

// round 15
// speedup vs baseline: 1.4228x; 1.1906x over previous
#include <cuda_runtime.h>
#include <cuda_fp16.h>
#include <cstdint>

#define N_USERS 100000
#define N_ITEMS 50000
#define N_NODES 150000
#define D 64
#define DH2 32             // D/2 half2 per node row (128B)
#define DU2 16             // D/4 uint2 per node row (128B)
#define DF2 32             // D/2 float2 per node row (256B)
#define NNZ 4800000
#define PAD 128            // slots per row (Poisson(32) max deg << 128)
#define PAD_SHIFT 7

// ---------------- device-global scratch (no allocations allowed) -----------
// NOTE: device globals are zero-initialized at module load; colvPad slots
// beyond each row's degree are NEVER written, so they stay {col=0, val=0.0f}
// forever -> reading them contributes v*x = 0 (harmless).
__device__ uint2 g_egoH[N_NODES * DU2];        // 19.2 MB fp16 ego
__device__ uint2 g_bufA[N_NODES * DU2];        // 19.2 MB hop-1 out (fp16)
__device__ uint2 g_bufB[N_NODES * DU2];        // 19.2 MB hop-2 out (fp16)
__device__ int2  g_colvPad[N_NODES * PAD + 32];// 153.6 MB padded CSR slots
__device__ int   g_cnt[N_NODES];               // per-row fill counters == degree

// ---------------------------------------------------------------------------
// Fused build kernel: every thread converts one float2 of ego to fp16
// (coalesced, BW-light); the first NNZ/4 threads ALSO scatter 4 COO edges
// into the padded CSR. The convert work hides inside the scatter's atomic
// latency shadow (measured issue=2.1% on the standalone scatter).
// ---------------------------------------------------------------------------
__global__ void __launch_bounds__(256) build_kernel(
    const float2* __restrict__ u, const float2* __restrict__ it,
    __half2* __restrict__ egoH,
    const int4* __restrict__ row4, const int4* __restrict__ col4,
    const float4* __restrict__ vals4)
{
    int i = blockIdx.x * blockDim.x + threadIdx.x;

    // ---- convert slice (all threads, i < 4.8M elements) ----
    const int total = N_NODES * DH2;
    const int nu = N_USERS * DF2;
    if (i < total) {
        float2 v = (i < nu) ? __ldcs(u + i) : __ldcs(it + (i - nu));
        egoH[i] = __float22half2_rn(v);
    }

    // ---- scatter slice (first NNZ/4 threads) ----
    if (i < NNZ / 4) {
        int4   r = __ldcs(row4 + i);
        int4   c = __ldcs(col4 + i);
        float4 v = __ldcs(vals4 + i);
        int p0 = atomicAdd(&g_cnt[r.x], 1) & (PAD - 1);
        int p1 = atomicAdd(&g_cnt[r.y], 1) & (PAD - 1);
        int p2 = atomicAdd(&g_cnt[r.z], 1) & (PAD - 1);
        int p3 = atomicAdd(&g_cnt[r.w], 1) & (PAD - 1);
        __stcs(&g_colvPad[((size_t)r.x << PAD_SHIFT) + p0],
               make_int2(c.x, __float_as_int(v.x)));
        __stcs(&g_colvPad[((size_t)r.y << PAD_SHIFT) + p1],
               make_int2(c.y, __float_as_int(v.y)));
        __stcs(&g_colvPad[((size_t)r.z << PAD_SHIFT) + p2],
               make_int2(c.z, __float_as_int(v.z)));
        __stcs(&g_colvPad[((size_t)r.w << PAD_SHIFT) + p3],
               make_int2(c.w, __float_as_int(v.w)));
    }
}

// ---------------------------------------------------------------------------
// Gather SpMM hop — EXACT R10 structure (proven 71.5us @ regs=32, occ=83%):
// 2 rows/warp, 16 lanes/row, lane owns uint2 (4 dims, 8B); 16-edge metadata
// chunks (128B coalesced) software-pipelined via shfl broadcast.
// Only change vs R10: prime + prefetch are UNCONDITIONAL (pad slots are
// guaranteed zero -> v=0 no-ops; indices stay within the row's 128 slots).
// MODE 1: x=egoH; yh=bufA, out_layer = y1
// MODE 2: x=bufA; yh=bufB
// MODE 3: x=bufB; out_all = (bufA + bufB + y3)/3
// ---------------------------------------------------------------------------
template<int MODE>
__global__ void __launch_bounds__(256) hop_kernel(
    const uint2* __restrict__ xh, uint2* __restrict__ yh,
    const uint2* __restrict__ y1h, const uint2* __restrict__ y2h,
    float2* __restrict__ out_all, float2* __restrict__ out_layer)
{
    int gwarp = (blockIdx.x * blockDim.x + threadIdx.x) >> 5;
    int lane  = threadIdx.x & 31;
    int half  = lane >> 4;
    int sub   = lane & 15;
    int row   = gwarp * 2 + half;
    if (row >= N_NODES) return;

    const unsigned mask = 0xFFFFu << (half << 4);
    int beg = row << PAD_SHIFT;
    int deg = min(g_cnt[row], PAD);
    int nfull = deg >> 4;

    float a0 = 0.f, a1 = 0.f, a2 = 0.f, a3 = 0.f;

    // prime chunk 0 (unconditional: pad slots are zeros)
    int2 cv = __ldcs(&g_colvPad[beg + sub]);
    int base = beg;

    for (int c = 0; c < nfull; c++) {
        int2 cur = cv;
        cv = __ldcs(&g_colvPad[base + 16 + sub]);          // unconditional prefetch
        #pragma unroll
        for (int j = 0; j < 16; j++) {
            int cx = __shfl_sync(mask, cur.x, j, 16);
            int vb = __shfl_sync(mask, cur.y, j, 16);
            uint2 h = __ldg(xh + (size_t)cx * DU2 + sub);
            float v = __int_as_float(vb);
            float2 f0 = __half22float2(*reinterpret_cast<__half2*>(&h.x));
            float2 f1 = __half22float2(*reinterpret_cast<__half2*>(&h.y));
            a0 = fmaf(v, f0.x, a0);
            a1 = fmaf(v, f0.y, a1);
            a2 = fmaf(v, f1.x, a2);
            a3 = fmaf(v, f1.y, a3);
        }
        base += 16;
    }

    int rem = deg - (nfull << 4);
    #pragma unroll
    for (int j = 0; j < 16; j++) {
        if (j < rem) {
            int cx = __shfl_sync(mask, cv.x, j, 16);
            int vb = __shfl_sync(mask, cv.y, j, 16);
            uint2 h = __ldg(xh + (size_t)cx * DU2 + sub);
            float v = __int_as_float(vb);
            float2 f0 = __half22float2(*reinterpret_cast<__half2*>(&h.x));
            float2 f1 = __half22float2(*reinterpret_cast<__half2*>(&h.y));
            a0 = fmaf(v, f0.x, a0);
            a1 = fmaf(v, f0.y, a1);
            a2 = fmaf(v, f1.x, a2);
            a3 = fmaf(v, f1.y, a3);
        }
    }

    size_t oh = (size_t)row * DU2 + sub;          // fp16 buffer slot
    size_t of = (size_t)row * DF2 + sub * 2;      // fp32 float2 slot (x2)

    if (MODE == 1 || MODE == 2) {
        __half2 p0 = __floats2half2_rn(a0, a1);
        __half2 p1 = __floats2half2_rn(a2, a3);
        uint2 packed;
        packed.x = *reinterpret_cast<unsigned*>(&p0);
        packed.y = *reinterpret_cast<unsigned*>(&p1);
        __stcs(&yh[oh], packed);
    }
    if (MODE == 1) {
        __stcs(&out_layer[of],     make_float2(a0, a1));
        __stcs(&out_layer[of + 1], make_float2(a2, a3));
    }
    if (MODE == 3) {
        const float s = 1.0f / 3.0f;
        uint2 u1 = __ldcs(y1h + oh);
        uint2 u2 = __ldcs(y2h + oh);
        float2 b10 = __half22float2(*reinterpret_cast<__half2*>(&u1.x));
        float2 b11 = __half22float2(*reinterpret_cast<__half2*>(&u1.y));
        float2 b20 = __half22float2(*reinterpret_cast<__half2*>(&u2.x));
        float2 b21 = __half22float2(*reinterpret_cast<__half2*>(&u2.y));
        __stcs(&out_all[of],
               make_float2((b10.x + b20.x + a0) * s, (b10.y + b20.y + a1) * s));
        __stcs(&out_all[of + 1],
               make_float2((b11.x + b21.x + a2) * s, (b11.y + b21.y + a3) * s));
    }
}

// ---------------------------------------------------------------------------
extern "C" void kernel_launch(void* const* d_in, const int* in_sizes, int n_in,
                              void* d_out, int out_size)
{
    const float2* user_e = (const float2*)d_in[0];
    const float2* item_e = (const float2*)d_in[1];
    const int*    row    = (const int*)d_in[2];
    const int*    col    = (const int*)d_in[3];
    const float*  vals   = (const float*)d_in[4];

    float2* out_all   = (float2*)d_out;
    float2* out_layer = out_all + (size_t)N_NODES * DF2;

    void* cntAddr;
    cudaGetSymbolAddress(&cntAddr, g_cnt);
    uint2 *egoH, *bufA, *bufB;
    cudaGetSymbolAddress((void**)&egoH, g_egoH);
    cudaGetSymbolAddress((void**)&bufA, g_bufA);
    cudaGetSymbolAddress((void**)&bufB, g_bufB);

    const int elemBlocks = (N_NODES * DH2 + 255) / 256;   // 18750 (covers scatter's 4688)
    const int hopWarps   = (N_NODES + 1) / 2;             // 2 rows per warp
    const int hopBlocks  = (hopWarps * 32 + 255) / 256;

    // ---- fused fp16-ego convert + one-pass padded CSR build ----
    cudaMemsetAsync(cntAddr, 0, N_NODES * sizeof(int));
    build_kernel<<<elemBlocks, 256>>>(user_e, item_e, (__half2*)egoH,
                                      (const int4*)row, (const int4*)col,
                                      (const float4*)vals);

    // ---- 3 hops; mean deferred to hop 3 ----
    hop_kernel<1><<<hopBlocks, 256>>>(egoH, bufA, nullptr, nullptr,
                                      out_all, out_layer);
    hop_kernel<2><<<hopBlocks, 256>>>(bufA, bufB, nullptr, nullptr,
                                      out_all, out_layer);
    hop_kernel<3><<<hopBlocks, 256>>>(bufB, nullptr, bufA, bufB,
                                      out_all, out_layer);
}